// round 1
// baseline (speedup 1.0000x reference)
#include <cuda_runtime.h>

// Problem constants (fixed shapes for this problem)
constexpr int T_ = 2048;   // query length
constexpr int S_ = 2048;   // key length
constexpr int B_ = 2;      // batch
constexpr int E_ = 1024;   // embed dim
constexpr int H_ = 16;     // heads
constexpr int D_ = 64;     // head dim
constexpr int M_ = T_ * B_; // 4096 rows for projection GEMMs

// Scratch (allocations are forbidden; __device__ globals are the sanctioned path)
__device__ float g_q[B_ * H_ * T_ * D_];
__device__ float g_k[B_ * H_ * S_ * D_];
__device__ float g_v[B_ * H_ * S_ * D_];
__device__ float g_ctx[T_ * B_ * E_];

// ---------------------------------------------------------------------------
// GEMM: C = A[M,E] @ W[E,E]^T + bias  (both operands K-major => A@B^T form)
// OUT_MODE 0: write to head-major [B,H,T,D] layout, value = (acc+bias)*scale
// OUT_MODE 1: write row-major [M,E], value = acc + bias
// Tile: 64x64, BK=16, 256 threads, 4x4 per-thread micro-tile.
// ---------------------------------------------------------------------------
template <int OUT_MODE>
__global__ void __launch_bounds__(256)
gemm_proj(const float* __restrict__ A, const float* __restrict__ W,
          const float* __restrict__ bias, float* __restrict__ C, float scale)
{
    constexpr int BK = 16;
    __shared__ float As[BK][64];  // [k][row]
    __shared__ float Bs[BK][64];  // [k][col]

    const int tid = threadIdx.x;
    const int ty  = tid >> 4;      // 0..15 -> rows
    const int tx  = tid & 15;      // 0..15 -> cols
    const int bm  = blockIdx.x * 64;
    const int bn  = blockIdx.y * 64;

    const int lr = tid >> 2;         // 0..63 tile row for loading
    const int lk = (tid & 3) * 4;    // 0..12 k offset for loading

    const float* Ap = A + (bm + lr) * E_ + lk;
    const float* Wp = W + (bn + lr) * E_ + lk;

    float acc[4][4] = {};

    for (int k0 = 0; k0 < E_; k0 += BK) {
        float4 av = *(const float4*)(Ap + k0);
        float4 bv = *(const float4*)(Wp + k0);
        As[lk + 0][lr] = av.x; As[lk + 1][lr] = av.y;
        As[lk + 2][lr] = av.z; As[lk + 3][lr] = av.w;
        Bs[lk + 0][lr] = bv.x; Bs[lk + 1][lr] = bv.y;
        Bs[lk + 2][lr] = bv.z; Bs[lk + 3][lr] = bv.w;
        __syncthreads();

        #pragma unroll
        for (int kk = 0; kk < BK; kk++) {
            float4 a4 = *(const float4*)&As[kk][ty * 4];
            float4 b4 = *(const float4*)&Bs[kk][tx * 4];
            float aa[4] = {a4.x, a4.y, a4.z, a4.w};
            float bb[4] = {b4.x, b4.y, b4.z, b4.w};
            #pragma unroll
            for (int i = 0; i < 4; i++)
                #pragma unroll
                for (int j = 0; j < 4; j++)
                    acc[i][j] += aa[i] * bb[j];
        }
        __syncthreads();
    }

    #pragma unroll
    for (int i = 0; i < 4; i++) {
        const int row = bm + ty * 4 + i;
        #pragma unroll
        for (int j = 0; j < 4; j++) {
            const int col = bn + tx * 4 + j;
            float val = (acc[i][j] + bias[col]) * scale;
            if (OUT_MODE == 0) {
                // row = t*B + b  (query/key/value are [T,B,E] row-major)
                const int t = row / B_;
                const int b = row % B_;
                const int h = col >> 6;
                const int dd = col & 63;
                C[((b * H_ + h) * T_ + t) * D_ + dd] = val;
            } else {
                C[row * E_ + col] = val;
            }
        }
    }
}

// ---------------------------------------------------------------------------
// Flash attention (fp32): per CTA one 64-row Q tile of one (b,h).
// Online softmax over S in 64-key tiles. attn_mask additive, key_padding adds -1e9.
// 256 threads = 16x16 grid; thread owns rows ty*4..+3, cols tx*4..+3.
// smem: qT[64][64] (d-major), kT[64][64] (d-major), v[64][64], p[64][64] = 64KB.
// ---------------------------------------------------------------------------
__global__ void __launch_bounds__(256)
flash_attn(const float* __restrict__ qg, const float* __restrict__ kg,
           const float* __restrict__ vg, const float* __restrict__ maskg,
           const unsigned char* __restrict__ kpg, float* __restrict__ ctx)
{
    extern __shared__ float sm[];
    float (*qsT)[64] = (float(*)[64])(sm);              // [dd][row]
    float (*ksT)[64] = (float(*)[64])(sm + 64 * 64);    // [dd][key]
    float (*vs)[64]  = (float(*)[64])(sm + 2 * 64 * 64);// [key][dd]
    float (*ps)[64]  = (float(*)[64])(sm + 3 * 64 * 64);// [row][key]

    const int tid = threadIdx.x;
    const int ty = tid >> 4;
    const int tx = tid & 15;
    const int t0 = blockIdx.x * 64;
    const int h  = blockIdx.y;
    const int b  = blockIdx.z;

    const float* qbase = qg + ((b * H_ + h) * T_ + t0) * D_;
    const float* kbase = kg + (b * H_ + h) * S_ * D_;
    const float* vbase = vg + (b * H_ + h) * S_ * D_;
    const unsigned char* kpb = kpg + b * S_;

    const int lr = tid >> 2;          // 0..63 tile row
    const int lc = (tid & 3) * 16;    // dd chunk base (16 floats per thread)

    // Load Q tile transposed (d-major)
    {
        const float* qp = qbase + lr * D_ + lc;
        #pragma unroll
        for (int c4 = 0; c4 < 16; c4 += 4) {
            float4 vq = *(const float4*)(qp + c4);
            qsT[lc + c4 + 0][lr] = vq.x; qsT[lc + c4 + 1][lr] = vq.y;
            qsT[lc + c4 + 2][lr] = vq.z; qsT[lc + c4 + 3][lr] = vq.w;
        }
    }

    float m[4], l[4], acc[4][4];
    #pragma unroll
    for (int i = 0; i < 4; i++) {
        m[i] = -1e30f; l[i] = 0.f;
        #pragma unroll
        for (int j = 0; j < 4; j++) acc[i][j] = 0.f;
    }

    for (int s0 = 0; s0 < S_; s0 += 64) {
        // Load K tile transposed, V tile direct
        {
            const float* kp_ = kbase + (s0 + lr) * D_ + lc;
            #pragma unroll
            for (int c4 = 0; c4 < 16; c4 += 4) {
                float4 vk = *(const float4*)(kp_ + c4);
                ksT[lc + c4 + 0][lr] = vk.x; ksT[lc + c4 + 1][lr] = vk.y;
                ksT[lc + c4 + 2][lr] = vk.z; ksT[lc + c4 + 3][lr] = vk.w;
            }
            const float* vp_ = vbase + (s0 + lr) * D_ + lc;
            #pragma unroll
            for (int c4 = 0; c4 < 16; c4 += 4) {
                *(float4*)&vs[lr][lc + c4] = *(const float4*)(vp_ + c4);
            }
        }
        __syncthreads();

        // Scores s[4][4] = q . k  (q already scaled by 1/sqrt(d))
        float s[4][4] = {};
        #pragma unroll 16
        for (int dd = 0; dd < D_; dd++) {
            float4 a4 = *(const float4*)&qsT[dd][ty * 4];
            float4 b4 = *(const float4*)&ksT[dd][tx * 4];
            float aa[4] = {a4.x, a4.y, a4.z, a4.w};
            float bb[4] = {b4.x, b4.y, b4.z, b4.w};
            #pragma unroll
            for (int i = 0; i < 4; i++)
                #pragma unroll
                for (int j = 0; j < 4; j++)
                    s[i][j] += aa[i] * bb[j];
        }

        // Masks
        const int r0g = t0 + ty * 4;
        const int c0g = s0 + tx * 4;
        #pragma unroll
        for (int j = 0; j < 4; j++) {
            const float kpadd = kpb[c0g + j] ? -1e9f : 0.f;
            #pragma unroll
            for (int i = 0; i < 4; i++)
                s[i][j] += maskg[(r0g + i) * S_ + c0g + j] + kpadd;
        }

        // Online softmax (row stats reduced across the 16 tx lanes, width=16)
        #pragma unroll
        for (int i = 0; i < 4; i++) {
            float rm = fmaxf(fmaxf(s[i][0], s[i][1]), fmaxf(s[i][2], s[i][3]));
            #pragma unroll
            for (int off = 8; off > 0; off >>= 1)
                rm = fmaxf(rm, __shfl_xor_sync(0xffffffffu, rm, off, 16));
            const float mnew = fmaxf(m[i], rm);
            const float corr = __expf(m[i] - mnew);
            m[i] = mnew;
            float rs = 0.f;
            #pragma unroll
            for (int j = 0; j < 4; j++) {
                s[i][j] = __expf(s[i][j] - mnew);
                rs += s[i][j];
            }
            #pragma unroll
            for (int off = 8; off > 0; off >>= 1)
                rs += __shfl_xor_sync(0xffffffffu, rs, off, 16);
            l[i] = l[i] * corr + rs;
            #pragma unroll
            for (int j = 0; j < 4; j++) acc[i][j] *= corr;
        }

        // Publish probabilities to smem
        #pragma unroll
        for (int i = 0; i < 4; i++)
            *(float4*)&ps[ty * 4 + i][tx * 4] =
                make_float4(s[i][0], s[i][1], s[i][2], s[i][3]);
        __syncthreads();

        // acc += P @ V   (thread owns rows ty*4..+3, d-cols tx*4..+3)
        #pragma unroll 16
        for (int key = 0; key < 64; key++) {
            float4 b4 = *(const float4*)&vs[key][tx * 4];
            float bb[4] = {b4.x, b4.y, b4.z, b4.w};
            #pragma unroll
            for (int i = 0; i < 4; i++) {
                const float a = ps[ty * 4 + i][key];
                acc[i][0] += a * bb[0];
                acc[i][1] += a * bb[1];
                acc[i][2] += a * bb[2];
                acc[i][3] += a * bb[3];
            }
        }
        __syncthreads();
    }

    // Normalize + write context in [T,B,E] so the O-projection is a plain GEMM
    #pragma unroll
    for (int i = 0; i < 4; i++) {
        const float inv = 1.f / l[i];
        const int t = t0 + ty * 4 + i;
        #pragma unroll
        for (int j = 0; j < 4; j++) {
            const int col = h * D_ + tx * 4 + j;
            ctx[(t * B_ + b) * E_ + col] = acc[i][j] * inv;
        }
    }
}

// ---------------------------------------------------------------------------
// Launch
// ---------------------------------------------------------------------------
extern "C" void kernel_launch(void* const* d_in, const int* in_sizes, int n_in,
                              void* d_out, int out_size)
{
    const float* query = (const float*)d_in[0];
    const float* key   = (const float*)d_in[1];
    const float* value = (const float*)d_in[2];
    const float* amask = (const float*)d_in[3];
    const unsigned char* kpad = (const unsigned char*)d_in[4];
    const float* Wq = (const float*)d_in[5];
    const float* bq = (const float*)d_in[6];
    const float* Wk = (const float*)d_in[7];
    const float* bk = (const float*)d_in[8];
    const float* Wv = (const float*)d_in[9];
    const float* bv = (const float*)d_in[10];
    const float* Wo = (const float*)d_in[11];
    const float* bo = (const float*)d_in[12];
    float* out = (float*)d_out;

    float *qp, *kp, *vp, *cp;
    cudaGetSymbolAddress((void**)&qp, g_q);
    cudaGetSymbolAddress((void**)&kp, g_k);
    cudaGetSymbolAddress((void**)&vp, g_v);
    cudaGetSymbolAddress((void**)&cp, g_ctx);

    const int smem_bytes = 4 * 64 * 64 * (int)sizeof(float); // 64 KB
    cudaFuncSetAttribute(flash_attn, cudaFuncAttributeMaxDynamicSharedMemorySize,
                         smem_bytes);

    dim3 gblk(256);
    dim3 ggrid(M_ / 64, E_ / 64);

    // Q/K/V projections into head-major scratch (Q pre-scaled by 1/sqrt(64))
    gemm_proj<0><<<ggrid, gblk>>>(query, Wq, bq, qp, 0.125f);
    gemm_proj<0><<<ggrid, gblk>>>(key,   Wk, bk, kp, 1.0f);
    gemm_proj<0><<<ggrid, gblk>>>(value, Wv, bv, vp, 1.0f);

    // Fused attention
    dim3 fgrid(T_ / 64, H_, B_);
    flash_attn<<<fgrid, gblk, smem_bytes>>>(qp, kp, vp, amask, kpad, cp);

    // Output projection
    gemm_proj<1><<<ggrid, gblk>>>(cp, Wo, bo, out, 1.0f);
}

// round 3
// speedup vs baseline: 1.4450x; 1.4450x over previous
#include <cuda_runtime.h>
#include <cuda_bf16.h>
#include <cstdint>

// Problem constants (fixed shapes)
constexpr int T_ = 2048;
constexpr int S_ = 2048;
constexpr int B_ = 2;
constexpr int E_ = 1024;
constexpr int H_ = 16;
constexpr int D_ = 64;
constexpr int M_ = T_ * B_;   // 4096

// ---------------------------------------------------------------------------
// Scratch (__device__ globals; allocations forbidden)
// ---------------------------------------------------------------------------
__device__ float g_q[B_ * H_ * T_ * D_];
__device__ float g_k[B_ * H_ * S_ * D_];
__device__ float g_v[B_ * H_ * S_ * D_];
__device__ float g_ctx[T_ * B_ * E_];

__device__ __nv_bfloat16 g_qh[T_ * B_ * E_], g_ql[T_ * B_ * E_];
__device__ __nv_bfloat16 g_kh[S_ * B_ * E_], g_kl[S_ * B_ * E_];
__device__ __nv_bfloat16 g_vh[S_ * B_ * E_], g_vl[S_ * B_ * E_];
__device__ __nv_bfloat16 g_ch[T_ * B_ * E_], g_cl[T_ * B_ * E_];
__device__ __nv_bfloat16 g_wh[4][E_ * E_], g_wl[4][E_ * E_];

// ---------------------------------------------------------------------------
// PTX helpers (all generic-PTX; no arch-variant instructions)
// ---------------------------------------------------------------------------
__device__ __forceinline__ uint32_t smem_u32(const void* p) {
    uint32_t a;
    asm("{ .reg .u64 t; cvta.to.shared.u64 t, %1; cvt.u32.u64 %0, t; }"
        : "=r"(a) : "l"(p));
    return a;
}
__device__ __forceinline__ void cp16(uint32_t dst, const void* src) {
    asm volatile("cp.async.cg.shared.global [%0], [%1], 16;" :: "r"(dst), "l"(src));
}
__device__ __forceinline__ void cp_commit() {
    asm volatile("cp.async.commit_group;" ::: "memory");
}
template <int N>
__device__ __forceinline__ void cp_wait() {
    asm volatile("cp.async.wait_group %0;" :: "n"(N) : "memory");
}
__device__ __forceinline__ void ldsm4(uint32_t& r0, uint32_t& r1, uint32_t& r2,
                                      uint32_t& r3, uint32_t addr) {
    asm volatile("ldmatrix.sync.aligned.m8n8.x4.shared.b16 {%0,%1,%2,%3}, [%4];"
                 : "=r"(r0), "=r"(r1), "=r"(r2), "=r"(r3) : "r"(addr));
}
__device__ __forceinline__ void mma_bf16(float* c, const uint32_t* a,
                                         uint32_t b0, uint32_t b1) {
    asm volatile(
        "mma.sync.aligned.m16n8k16.row.col.f32.bf16.bf16.f32 "
        "{%0,%1,%2,%3}, {%4,%5,%6,%7}, {%8,%9}, {%0,%1,%2,%3};"
        : "+f"(c[0]), "+f"(c[1]), "+f"(c[2]), "+f"(c[3])
        : "r"(a[0]), "r"(a[1]), "r"(a[2]), "r"(a[3]), "r"(b0), "r"(b1));
}

// ---------------------------------------------------------------------------
// Convert fp32 -> (bf16 hi, bf16 lo)
// ---------------------------------------------------------------------------
__global__ void __launch_bounds__(256)
convert_hilo(const float4* __restrict__ in, uint2* __restrict__ hi,
             uint2* __restrict__ lo, int n4)
{
    int i = blockIdx.x * 256 + threadIdx.x;
    if (i >= n4) return;
    float4 v = in[i];
    __nv_bfloat16 h[4], l[4];
    float f[4] = {v.x, v.y, v.z, v.w};
    #pragma unroll
    for (int j = 0; j < 4; j++) {
        h[j] = __float2bfloat16(f[j]);
        l[j] = __float2bfloat16(f[j] - __bfloat162float(h[j]));
    }
    hi[i] = *reinterpret_cast<uint2*>(h);
    lo[i] = *reinterpret_cast<uint2*>(l);
}

// ---------------------------------------------------------------------------
// HMMA GEMM: C[M,N] = (A @ W^T + bias) * scale via 3-term bf16 split.
// A: [M,1024] K-major bf16 (hi/lo). W: [N,1024] K-major bf16 (hi/lo).
// CTA 128x128, BK=32, 8 warps (2x4), warp tile 64x32, cp.async double buffer.
// smem per stage: 4 tensors x (128 rows x 32 bf16 = 8KB) = 32KB; 2 stages.
// Swizzle: 64B rows, byte ^ ((row&3)<<4).
// OUT_MODE 0: head-major [B,H,T,D] scatter. OUT_MODE 1: row-major [M,E].
// ---------------------------------------------------------------------------
constexpr int STAGE_BYTES = 32768;
constexpr int GEMM_SMEM   = 2 * STAGE_BYTES;   // 64 KB

__device__ __forceinline__ uint32_t sw_addr(int row, int byte_in_row) {
    uint32_t b = (uint32_t)(row * 64 + byte_in_row);
    return b ^ (((uint32_t)row & 3u) << 4);
}

__device__ __forceinline__ void load_stage(
    uint32_t sdst, const __nv_bfloat16* __restrict__ Ah,
    const __nv_bfloat16* __restrict__ Al, const __nv_bfloat16* __restrict__ Wh,
    const __nv_bfloat16* __restrict__ Wl, int bm, int bn, int k0, int tid)
{
    const __nv_bfloat16* srcs[4] = {Ah, Al, Wh, Wl};
    const int rbase[4] = {bm, bm, bn, bn};
    #pragma unroll
    for (int i = 0; i < 8; i++) {
        const int id = tid + i * 256;          // 0..2047
        const int sub = id >> 9;               // tensor
        const int lin = id & 511;              // 0..511
        const int row = lin >> 2;              // 0..127
        const int c   = lin & 3;               // 16B chunk in row
        cp16(sdst + sub * 8192 + sw_addr(row, c * 16),
             srcs[sub] + (size_t)(rbase[sub] + row) * E_ + k0 + c * 8);
    }
}

template <int OUT_MODE>
__global__ void __launch_bounds__(256, 1)
gemm_tc(const __nv_bfloat16* __restrict__ Ah, const __nv_bfloat16* __restrict__ Al,
        const __nv_bfloat16* __restrict__ Wh, const __nv_bfloat16* __restrict__ Wl,
        const float* __restrict__ bias, float* __restrict__ C, float scale)
{
    extern __shared__ char smem[];
    const uint32_t sbase = smem_u32(smem);
    const int tid = threadIdx.x;
    const int warp = tid >> 5;
    const int lane = tid & 31;
    const int bm = blockIdx.x * 128;
    const int bn = blockIdx.y * 128;

    const int wm = (warp >> 2) * 64;   // warp row offset in tile (0/64)
    const int wn = (warp & 3) * 32;    // warp col offset in tile (0/32/64/96)

    float acc[4][4][4] = {};           // [mi][ni][frag]

    // per-lane ldmatrix row/seg
    const int lrow = lane & 15;
    const int lseg = lane >> 4;        // 0/1 -> 16B segment within k16

    load_stage(sbase, Ah, Al, Wh, Wl, bm, bn, 0, tid);
    cp_commit();

    for (int chunk = 0; chunk < 32; chunk++) {
        const int s = chunk & 1;
        if (chunk < 31) {
            load_stage(sbase + (s ^ 1) * STAGE_BYTES, Ah, Al, Wh, Wl,
                       bm, bn, (chunk + 1) * 32, tid);
            cp_commit();
            cp_wait<1>();
        } else {
            cp_wait<0>();
        }
        __syncthreads();

        const uint32_t st = sbase + s * STAGE_BYTES;
        #pragma unroll
        for (int kk = 0; kk < 2; kk++) {       // two k16 steps in BK=32
            const int chunk16 = kk * 2 + lseg; // 16B chunk index 0..3
            uint32_t ah[4][4], al[4][4], bh[2][4], bl[2][4];
            #pragma unroll
            for (int mi = 0; mi < 4; mi++) {
                const int row = wm + mi * 16 + lrow;
                ldsm4(ah[mi][0], ah[mi][1], ah[mi][2], ah[mi][3],
                      st + 0    + sw_addr(row, chunk16 * 16));
                ldsm4(al[mi][0], al[mi][1], al[mi][2], al[mi][3],
                      st + 8192 + sw_addr(row, chunk16 * 16));
            }
            #pragma unroll
            for (int nb = 0; nb < 2; nb++) {
                const int row = wn + nb * 16 + lrow;
                ldsm4(bh[nb][0], bh[nb][1], bh[nb][2], bh[nb][3],
                      st + 16384 + sw_addr(row, chunk16 * 16));
                ldsm4(bl[nb][0], bl[nb][1], bl[nb][2], bl[nb][3],
                      st + 24576 + sw_addr(row, chunk16 * 16));
            }
            #pragma unroll
            for (int mi = 0; mi < 4; mi++) {
                #pragma unroll
                for (int ni = 0; ni < 4; ni++) {
                    const int nb = ni >> 1, hp = ni & 1;
                    // B frag regs: {r[hp], r[hp+2]} of the x4 load
                    mma_bf16(acc[mi][ni], ah[mi], bh[nb][hp], bh[nb][hp + 2]);
                    mma_bf16(acc[mi][ni], ah[mi], bl[nb][hp], bl[nb][hp + 2]);
                    mma_bf16(acc[mi][ni], al[mi], bh[nb][hp], bh[nb][hp + 2]);
                }
            }
        }
        __syncthreads();
    }

    // Epilogue: acc frag (r, c): c0,c1 -> row lane/4, col (lane%4)*2; c2,c3 -> +8 row
    #pragma unroll
    for (int mi = 0; mi < 4; mi++) {
        #pragma unroll
        for (int ni = 0; ni < 4; ni++) {
            const int col = bn + wn + ni * 8 + (lane & 3) * 2;
            const float b0 = bias[col], b1 = bias[col + 1];
            #pragma unroll
            for (int half = 0; half < 2; half++) {
                const int m = bm + wm + mi * 16 + (lane >> 2) + half * 8;
                float2 o;
                o.x = (acc[mi][ni][half * 2 + 0] + b0) * scale;
                o.y = (acc[mi][ni][half * 2 + 1] + b1) * scale;
                if (OUT_MODE == 0) {
                    const int t = m >> 1, b = m & 1;   // m = t*B + b, B=2
                    const int h = col >> 6, dd = col & 63;
                    *(float2*)&C[((size_t)(b * H_ + h) * T_ + t) * D_ + dd] = o;
                } else {
                    *(float2*)&C[(size_t)m * E_ + col] = o;
                }
            }
        }
    }
}

// ---------------------------------------------------------------------------
// Flash attention (fp32 SIMT) — unchanged from R1 (passed, rel_err 1.5e-6)
// ---------------------------------------------------------------------------
__global__ void __launch_bounds__(256)
flash_attn(const float* __restrict__ qg, const float* __restrict__ kg,
           const float* __restrict__ vg, const float* __restrict__ maskg,
           const unsigned char* __restrict__ kpg, float* __restrict__ ctx)
{
    extern __shared__ float sm[];
    float (*qsT)[64] = (float(*)[64])(sm);
    float (*ksT)[64] = (float(*)[64])(sm + 64 * 64);
    float (*vs)[64]  = (float(*)[64])(sm + 2 * 64 * 64);
    float (*ps)[64]  = (float(*)[64])(sm + 3 * 64 * 64);

    const int tid = threadIdx.x;
    const int ty = tid >> 4;
    const int tx = tid & 15;
    const int t0 = blockIdx.x * 64;
    const int h  = blockIdx.y;
    const int b  = blockIdx.z;

    const float* qbase = qg + ((b * H_ + h) * T_ + t0) * D_;
    const float* kbase = kg + (b * H_ + h) * S_ * D_;
    const float* vbase = vg + (b * H_ + h) * S_ * D_;
    const unsigned char* kpb = kpg + b * S_;

    const int lr = tid >> 2;
    const int lc = (tid & 3) * 16;

    {
        const float* qp = qbase + lr * D_ + lc;
        #pragma unroll
        for (int c4 = 0; c4 < 16; c4 += 4) {
            float4 vq = *(const float4*)(qp + c4);
            qsT[lc + c4 + 0][lr] = vq.x; qsT[lc + c4 + 1][lr] = vq.y;
            qsT[lc + c4 + 2][lr] = vq.z; qsT[lc + c4 + 3][lr] = vq.w;
        }
    }

    float m[4], l[4], acc[4][4];
    #pragma unroll
    for (int i = 0; i < 4; i++) {
        m[i] = -1e30f; l[i] = 0.f;
        #pragma unroll
        for (int j = 0; j < 4; j++) acc[i][j] = 0.f;
    }

    for (int s0 = 0; s0 < S_; s0 += 64) {
        {
            const float* kp_ = kbase + (s0 + lr) * D_ + lc;
            #pragma unroll
            for (int c4 = 0; c4 < 16; c4 += 4) {
                float4 vk = *(const float4*)(kp_ + c4);
                ksT[lc + c4 + 0][lr] = vk.x; ksT[lc + c4 + 1][lr] = vk.y;
                ksT[lc + c4 + 2][lr] = vk.z; ksT[lc + c4 + 3][lr] = vk.w;
            }
            const float* vp_ = vbase + (s0 + lr) * D_ + lc;
            #pragma unroll
            for (int c4 = 0; c4 < 16; c4 += 4) {
                *(float4*)&vs[lr][lc + c4] = *(const float4*)(vp_ + c4);
            }
        }
        __syncthreads();

        float s[4][4] = {};
        #pragma unroll 16
        for (int dd = 0; dd < D_; dd++) {
            float4 a4 = *(const float4*)&qsT[dd][ty * 4];
            float4 b4 = *(const float4*)&ksT[dd][tx * 4];
            float aa[4] = {a4.x, a4.y, a4.z, a4.w};
            float bb[4] = {b4.x, b4.y, b4.z, b4.w};
            #pragma unroll
            for (int i = 0; i < 4; i++)
                #pragma unroll
                for (int j = 0; j < 4; j++)
                    s[i][j] += aa[i] * bb[j];
        }

        const int r0g = t0 + ty * 4;
        const int c0g = s0 + tx * 4;
        #pragma unroll
        for (int j = 0; j < 4; j++) {
            const float kpadd = kpb[c0g + j] ? -1e9f : 0.f;
            #pragma unroll
            for (int i = 0; i < 4; i++)
                s[i][j] += maskg[(r0g + i) * S_ + c0g + j] + kpadd;
        }

        #pragma unroll
        for (int i = 0; i < 4; i++) {
            float rm = fmaxf(fmaxf(s[i][0], s[i][1]), fmaxf(s[i][2], s[i][3]));
            #pragma unroll
            for (int off = 8; off > 0; off >>= 1)
                rm = fmaxf(rm, __shfl_xor_sync(0xffffffffu, rm, off, 16));
            const float mnew = fmaxf(m[i], rm);
            const float corr = __expf(m[i] - mnew);
            m[i] = mnew;
            float rs = 0.f;
            #pragma unroll
            for (int j = 0; j < 4; j++) {
                s[i][j] = __expf(s[i][j] - mnew);
                rs += s[i][j];
            }
            #pragma unroll
            for (int off = 8; off > 0; off >>= 1)
                rs += __shfl_xor_sync(0xffffffffu, rs, off, 16);
            l[i] = l[i] * corr + rs;
            #pragma unroll
            for (int j = 0; j < 4; j++) acc[i][j] *= corr;
        }

        #pragma unroll
        for (int i = 0; i < 4; i++)
            *(float4*)&ps[ty * 4 + i][tx * 4] =
                make_float4(s[i][0], s[i][1], s[i][2], s[i][3]);
        __syncthreads();

        #pragma unroll 16
        for (int key = 0; key < 64; key++) {
            float4 b4 = *(const float4*)&vs[key][tx * 4];
            float bb[4] = {b4.x, b4.y, b4.z, b4.w};
            #pragma unroll
            for (int i = 0; i < 4; i++) {
                const float a = ps[ty * 4 + i][key];
                acc[i][0] += a * bb[0];
                acc[i][1] += a * bb[1];
                acc[i][2] += a * bb[2];
                acc[i][3] += a * bb[3];
            }
        }
        __syncthreads();
    }

    #pragma unroll
    for (int i = 0; i < 4; i++) {
        const float inv = 1.f / l[i];
        const int t = t0 + ty * 4 + i;
        #pragma unroll
        for (int j = 0; j < 4; j++) {
            const int col = h * D_ + tx * 4 + j;
            ctx[(t * B_ + b) * E_ + col] = acc[i][j] * inv;
        }
    }
}

// ---------------------------------------------------------------------------
// Launch
// ---------------------------------------------------------------------------
extern "C" void kernel_launch(void* const* d_in, const int* in_sizes, int n_in,
                              void* d_out, int out_size)
{
    const float* query = (const float*)d_in[0];
    const float* key   = (const float*)d_in[1];
    const float* value = (const float*)d_in[2];
    const float* amask = (const float*)d_in[3];
    const unsigned char* kpad = (const unsigned char*)d_in[4];
    const float* Wq = (const float*)d_in[5];
    const float* bq = (const float*)d_in[6];
    const float* Wk = (const float*)d_in[7];
    const float* bk = (const float*)d_in[8];
    const float* Wv = (const float*)d_in[9];
    const float* bv = (const float*)d_in[10];
    const float* Wo = (const float*)d_in[11];
    const float* bo = (const float*)d_in[12];
    float* out = (float*)d_out;

    float *qp, *kp, *vp, *cp;
    cudaGetSymbolAddress((void**)&qp, g_q);
    cudaGetSymbolAddress((void**)&kp, g_k);
    cudaGetSymbolAddress((void**)&vp, g_v);
    cudaGetSymbolAddress((void**)&cp, g_ctx);

    __nv_bfloat16 *qh, *ql, *kh, *kl, *vh, *vl, *ch, *cl, *wh, *wl;
    cudaGetSymbolAddress((void**)&qh, g_qh); cudaGetSymbolAddress((void**)&ql, g_ql);
    cudaGetSymbolAddress((void**)&kh, g_kh); cudaGetSymbolAddress((void**)&kl, g_kl);
    cudaGetSymbolAddress((void**)&vh, g_vh); cudaGetSymbolAddress((void**)&vl, g_vl);
    cudaGetSymbolAddress((void**)&ch, g_ch); cudaGetSymbolAddress((void**)&cl, g_cl);
    cudaGetSymbolAddress((void**)&wh, g_wh); cudaGetSymbolAddress((void**)&wl, g_wl);

    const int flash_smem = 4 * 64 * 64 * (int)sizeof(float);
    cudaFuncSetAttribute(flash_attn, cudaFuncAttributeMaxDynamicSharedMemorySize,
                         flash_smem);
    cudaFuncSetAttribute(gemm_tc<0>, cudaFuncAttributeMaxDynamicSharedMemorySize,
                         GEMM_SMEM);
    cudaFuncSetAttribute(gemm_tc<1>, cudaFuncAttributeMaxDynamicSharedMemorySize,
                         GEMM_SMEM);

    const int nIn4 = T_ * B_ * E_ / 4;
    const int nW4  = E_ * E_ / 4;

    convert_hilo<<<(nIn4 + 255) / 256, 256>>>((const float4*)query, (uint2*)qh, (uint2*)ql, nIn4);
    convert_hilo<<<(nIn4 + 255) / 256, 256>>>((const float4*)key,   (uint2*)kh, (uint2*)kl, nIn4);
    convert_hilo<<<(nIn4 + 255) / 256, 256>>>((const float4*)value, (uint2*)vh, (uint2*)vl, nIn4);
    convert_hilo<<<(nW4 + 255) / 256, 256>>>((const float4*)Wq, (uint2*)(wh + 0 * E_ * E_), (uint2*)(wl + 0 * E_ * E_), nW4);
    convert_hilo<<<(nW4 + 255) / 256, 256>>>((const float4*)Wk, (uint2*)(wh + 1 * E_ * E_), (uint2*)(wl + 1 * E_ * E_), nW4);
    convert_hilo<<<(nW4 + 255) / 256, 256>>>((const float4*)Wv, (uint2*)(wh + 2 * E_ * E_), (uint2*)(wl + 2 * E_ * E_), nW4);
    convert_hilo<<<(nW4 + 255) / 256, 256>>>((const float4*)Wo, (uint2*)(wh + 3 * E_ * E_), (uint2*)(wl + 3 * E_ * E_), nW4);

    dim3 ggrid(M_ / 128, E_ / 128);
    gemm_tc<0><<<ggrid, 256, GEMM_SMEM>>>(qh, ql, wh + 0 * E_ * E_, wl + 0 * E_ * E_, bq, qp, 0.125f);
    gemm_tc<0><<<ggrid, 256, GEMM_SMEM>>>(kh, kl, wh + 1 * E_ * E_, wl + 1 * E_ * E_, bk, kp, 1.0f);
    gemm_tc<0><<<ggrid, 256, GEMM_SMEM>>>(vh, vl, wh + 2 * E_ * E_, wl + 2 * E_ * E_, bv, vp, 1.0f);

    dim3 fgrid(T_ / 64, H_, B_);
    flash_attn<<<fgrid, 256, flash_smem>>>(qp, kp, vp, amask, kpad, cp);

    convert_hilo<<<(nIn4 + 255) / 256, 256>>>((const float4*)cp, (uint2*)ch, (uint2*)cl, nIn4);
    gemm_tc<1><<<ggrid, 256, GEMM_SMEM>>>(ch, cl, wh + 3 * E_ * E_, wl + 3 * E_ * E_, bo, out, 1.0f);
}

// round 4
// speedup vs baseline: 2.7093x; 1.8750x over previous
#include <cuda_runtime.h>
#include <cuda_bf16.h>
#include <cstdint>

// Problem constants (fixed shapes)
constexpr int T_ = 2048;
constexpr int S_ = 2048;
constexpr int B_ = 2;
constexpr int E_ = 1024;
constexpr int H_ = 16;
constexpr int D_ = 64;
constexpr int M_ = T_ * B_;   // 4096

// ---------------------------------------------------------------------------
// Scratch (__device__ globals; allocations forbidden)
// ---------------------------------------------------------------------------
// converted inputs (K-major [M,E])
__device__ __nv_bfloat16 g_iqh[M_ * E_], g_iql[M_ * E_];
__device__ __nv_bfloat16 g_ikh[M_ * E_], g_ikl[M_ * E_];
__device__ __nv_bfloat16 g_ivh[M_ * E_], g_ivl[M_ * E_];
// converted weights (K-major [E,E]) q,k,v,o
__device__ __nv_bfloat16 g_wh[4][E_ * E_], g_wl[4][E_ * E_];
// projected q/k/v, head-major [B,H,T,D]
__device__ __nv_bfloat16 g_pqh[B_ * H_ * T_ * D_], g_pql[B_ * H_ * T_ * D_];
__device__ __nv_bfloat16 g_pkh[B_ * H_ * S_ * D_], g_pkl[B_ * H_ * S_ * D_];
__device__ __nv_bfloat16 g_pvh[B_ * H_ * S_ * D_], g_pvl[B_ * H_ * S_ * D_];
// attention context [M,E]
__device__ __nv_bfloat16 g_ch[M_ * E_], g_cl[M_ * E_];
// key padding as float additive mask
__device__ float g_kpf[B_ * S_];

// ---------------------------------------------------------------------------
// PTX helpers (generic PTX only — no sm_103a-gated instructions)
// ---------------------------------------------------------------------------
__device__ __forceinline__ uint32_t smem_u32(const void* p) {
    uint32_t a;
    asm("{ .reg .u64 t; cvta.to.shared.u64 t, %1; cvt.u32.u64 %0, t; }"
        : "=r"(a) : "l"(p));
    return a;
}
__device__ __forceinline__ void cp16(uint32_t dst, const void* src) {
    asm volatile("cp.async.cg.shared.global [%0], [%1], 16;" :: "r"(dst), "l"(src));
}
__device__ __forceinline__ void cp_commit() {
    asm volatile("cp.async.commit_group;" ::: "memory");
}
template <int N>
__device__ __forceinline__ void cp_wait() {
    asm volatile("cp.async.wait_group %0;" :: "n"(N) : "memory");
}
__device__ __forceinline__ void ldsm4(uint32_t& r0, uint32_t& r1, uint32_t& r2,
                                      uint32_t& r3, uint32_t addr) {
    asm volatile("ldmatrix.sync.aligned.m8n8.x4.shared.b16 {%0,%1,%2,%3}, [%4];"
                 : "=r"(r0), "=r"(r1), "=r"(r2), "=r"(r3) : "r"(addr));
}
__device__ __forceinline__ void ldsm4t(uint32_t* r, uint32_t addr) {
    asm volatile("ldmatrix.sync.aligned.m8n8.x4.trans.shared.b16 {%0,%1,%2,%3}, [%4];"
                 : "=r"(r[0]), "=r"(r[1]), "=r"(r[2]), "=r"(r[3]) : "r"(addr));
}
__device__ __forceinline__ void mma_bf16(float* c, const uint32_t* a,
                                         uint32_t b0, uint32_t b1) {
    asm volatile(
        "mma.sync.aligned.m16n8k16.row.col.f32.bf16.bf16.f32 "
        "{%0,%1,%2,%3}, {%4,%5,%6,%7}, {%8,%9}, {%0,%1,%2,%3};"
        : "+f"(c[0]), "+f"(c[1]), "+f"(c[2]), "+f"(c[3])
        : "r"(a[0]), "r"(a[1]), "r"(a[2]), "r"(a[3]), "r"(b0), "r"(b1));
}
__device__ __forceinline__ uint32_t packbf(float x, float y) {
    __nv_bfloat162 t = __floats2bfloat162_rn(x, y);
    return *reinterpret_cast<uint32_t*>(&t);
}
__device__ __forceinline__ float2 unpackbf(uint32_t u) {
    __nv_bfloat162 t = *reinterpret_cast<__nv_bfloat162*>(&u);
    return make_float2(__bfloat162float(t.x), __bfloat162float(t.y));
}

// ---------------------------------------------------------------------------
// Converts
// ---------------------------------------------------------------------------
__global__ void __launch_bounds__(256)
convert_hilo(const float4* __restrict__ in, uint2* __restrict__ hi,
             uint2* __restrict__ lo, int n4)
{
    int i = blockIdx.x * 256 + threadIdx.x;
    if (i >= n4) return;
    float4 v = in[i];
    __nv_bfloat16 h[4], l[4];
    float f[4] = {v.x, v.y, v.z, v.w};
    #pragma unroll
    for (int j = 0; j < 4; j++) {
        h[j] = __float2bfloat16(f[j]);
        l[j] = __float2bfloat16(f[j] - __bfloat162float(h[j]));
    }
    hi[i] = *reinterpret_cast<uint2*>(h);
    lo[i] = *reinterpret_cast<uint2*>(l);
}

__global__ void kpad_to_float(const unsigned char* __restrict__ kp,
                              float* __restrict__ out, int n)
{
    int i = blockIdx.x * 256 + threadIdx.x;
    if (i < n) out[i] = kp[i] ? -1e9f : 0.f;
}

// ---------------------------------------------------------------------------
// HMMA GEMM: C = (A @ W^T + bias) * scale, 3-term bf16 split.
// CTA 128x128, BK=32, 8 warps, warp tile 64x32, cp.async double buffer.
// OUT_MODE 0: bf16 hi/lo head-major [B,H,T,D]. OUT_MODE 1: fp32 [M,E].
// ---------------------------------------------------------------------------
constexpr int STAGE_BYTES = 32768;
constexpr int GEMM_SMEM   = 2 * STAGE_BYTES;

__device__ __forceinline__ uint32_t sw_addr(int row, int byte_in_row) {
    uint32_t b = (uint32_t)(row * 64 + byte_in_row);
    return b ^ (((uint32_t)row & 3u) << 4);
}

__device__ __forceinline__ void load_stage(
    uint32_t sdst, const __nv_bfloat16* __restrict__ Ah,
    const __nv_bfloat16* __restrict__ Al, const __nv_bfloat16* __restrict__ Wh,
    const __nv_bfloat16* __restrict__ Wl, int bm, int bn, int k0, int tid)
{
    const __nv_bfloat16* srcs[4] = {Ah, Al, Wh, Wl};
    const int rbase[4] = {bm, bm, bn, bn};
    #pragma unroll
    for (int i = 0; i < 8; i++) {
        const int id = tid + i * 256;
        const int sub = id >> 9;
        const int lin = id & 511;
        const int row = lin >> 2;
        const int c   = lin & 3;
        cp16(sdst + sub * 8192 + sw_addr(row, c * 16),
             srcs[sub] + (size_t)(rbase[sub] + row) * E_ + k0 + c * 8);
    }
}

template <int OUT_MODE>
__global__ void __launch_bounds__(256, 1)
gemm_tc(const __nv_bfloat16* __restrict__ Ah, const __nv_bfloat16* __restrict__ Al,
        const __nv_bfloat16* __restrict__ Wh, const __nv_bfloat16* __restrict__ Wl,
        const float* __restrict__ bias, float* __restrict__ Cf,
        __nv_bfloat16* __restrict__ Chi, __nv_bfloat16* __restrict__ Clo,
        float scale)
{
    extern __shared__ char smem[];
    const uint32_t sbase = smem_u32(smem);
    const int tid = threadIdx.x;
    const int warp = tid >> 5;
    const int lane = tid & 31;
    const int bm = blockIdx.x * 128;
    const int bn = blockIdx.y * 128;

    const int wm = (warp >> 2) * 64;
    const int wn = (warp & 3) * 32;

    float acc[4][4][4] = {};
    const int lrow = lane & 15;
    const int lseg = lane >> 4;

    load_stage(sbase, Ah, Al, Wh, Wl, bm, bn, 0, tid);
    cp_commit();

    for (int chunk = 0; chunk < 32; chunk++) {
        const int s = chunk & 1;
        if (chunk < 31) {
            load_stage(sbase + (s ^ 1) * STAGE_BYTES, Ah, Al, Wh, Wl,
                       bm, bn, (chunk + 1) * 32, tid);
            cp_commit();
            cp_wait<1>();
        } else {
            cp_wait<0>();
        }
        __syncthreads();

        const uint32_t st = sbase + s * STAGE_BYTES;
        #pragma unroll
        for (int kk = 0; kk < 2; kk++) {
            const int chunk16 = kk * 2 + lseg;
            uint32_t ah[4][4], al[4][4], bh[2][4], bl[2][4];
            #pragma unroll
            for (int mi = 0; mi < 4; mi++) {
                const int row = wm + mi * 16 + lrow;
                ldsm4(ah[mi][0], ah[mi][1], ah[mi][2], ah[mi][3],
                      st + 0    + sw_addr(row, chunk16 * 16));
                ldsm4(al[mi][0], al[mi][1], al[mi][2], al[mi][3],
                      st + 8192 + sw_addr(row, chunk16 * 16));
            }
            #pragma unroll
            for (int nb = 0; nb < 2; nb++) {
                const int row = wn + nb * 16 + lrow;
                ldsm4(bh[nb][0], bh[nb][1], bh[nb][2], bh[nb][3],
                      st + 16384 + sw_addr(row, chunk16 * 16));
                ldsm4(bl[nb][0], bl[nb][1], bl[nb][2], bl[nb][3],
                      st + 24576 + sw_addr(row, chunk16 * 16));
            }
            #pragma unroll
            for (int mi = 0; mi < 4; mi++) {
                #pragma unroll
                for (int ni = 0; ni < 4; ni++) {
                    const int nb = ni >> 1, hp = ni & 1;
                    mma_bf16(acc[mi][ni], ah[mi], bh[nb][hp], bh[nb][hp + 2]);
                    mma_bf16(acc[mi][ni], ah[mi], bl[nb][hp], bl[nb][hp + 2]);
                    mma_bf16(acc[mi][ni], al[mi], bh[nb][hp], bh[nb][hp + 2]);
                }
            }
        }
        __syncthreads();
    }

    #pragma unroll
    for (int mi = 0; mi < 4; mi++) {
        #pragma unroll
        for (int ni = 0; ni < 4; ni++) {
            const int col = bn + wn + ni * 8 + (lane & 3) * 2;
            const float b0 = bias[col], b1 = bias[col + 1];
            #pragma unroll
            for (int half = 0; half < 2; half++) {
                const int m = bm + wm + mi * 16 + (lane >> 2) + half * 8;
                float ox = (acc[mi][ni][half * 2 + 0] + b0) * scale;
                float oy = (acc[mi][ni][half * 2 + 1] + b1) * scale;
                if (OUT_MODE == 0) {
                    const int t = m >> 1, b = m & 1;   // m = t*B + b, B=2
                    const int h = col >> 6, dd = col & 63;
                    const size_t idx = ((size_t)(b * H_ + h) * T_ + t) * D_ + dd;
                    uint32_t hp_ = packbf(ox, oy);
                    float2 hf = unpackbf(hp_);
                    uint32_t lp_ = packbf(ox - hf.x, oy - hf.y);
                    *(uint32_t*)&Chi[idx] = hp_;
                    *(uint32_t*)&Clo[idx] = lp_;
                } else {
                    float2 o = make_float2(ox, oy);
                    *(float2*)&Cf[(size_t)m * E_ + col] = o;
                }
            }
        }
    }
}

// ---------------------------------------------------------------------------
// Flash attention via HMMA, 3-term hi/lo split for QK^T and PV.
// CTA: 128 q-rows of one (b,h); 8 warps x 16 rows; 64-key tiles, double buffer.
// smem: Qh/Ql 128x64 (32KB) + 2 stages x (Kh,Kl,Vh,Vl 64x64 = 32KB) + kpad.
// ---------------------------------------------------------------------------
constexpr uint32_t FA_OFF_QL  = 16384;
constexpr uint32_t FA_OFF_ST  = 32768;
constexpr uint32_t FA_ST_B    = 32768;
constexpr uint32_t FA_OFF_KPF = 98304;
constexpr int FA_SMEM = 98304 + 512;

__device__ __forceinline__ uint32_t fa_off(int row, int chunk) {
    return (uint32_t)(row * 128 + ((chunk ^ (row & 7)) << 4));
}

__device__ __forceinline__ void fa_load_stage(
    uint32_t sbase, int stage,
    const __nv_bfloat16* __restrict__ kh, const __nv_bfloat16* __restrict__ kl,
    const __nv_bfloat16* __restrict__ vh, const __nv_bfloat16* __restrict__ vl,
    const float* __restrict__ kpf, int s0, int tid)
{
    const __nv_bfloat16* srcs[4] = {kh, kl, vh, vl};
    #pragma unroll
    for (int i = 0; i < 8; i++) {
        const int id = tid + i * 256;
        const int sub = id >> 9;
        const int lin = id & 511;
        const int row = lin >> 3;
        const int c   = lin & 7;
        cp16(sbase + FA_OFF_ST + stage * FA_ST_B + sub * 8192 + fa_off(row, c),
             srcs[sub] + (size_t)(s0 + row) * D_ + c * 8);
    }
    if (tid < 16)
        cp16(sbase + FA_OFF_KPF + stage * 256 + tid * 16, kpf + s0 + tid * 4);
}

__global__ void __launch_bounds__(256)
flash_mma(const __nv_bfloat16* __restrict__ qh_g, const __nv_bfloat16* __restrict__ ql_g,
          const __nv_bfloat16* __restrict__ kh_g, const __nv_bfloat16* __restrict__ kl_g,
          const __nv_bfloat16* __restrict__ vh_g, const __nv_bfloat16* __restrict__ vl_g,
          const float* __restrict__ maskg, const float* __restrict__ kpf_g,
          __nv_bfloat16* __restrict__ ch, __nv_bfloat16* __restrict__ cl)
{
    extern __shared__ char smem[];
    const uint32_t sbase = smem_u32(smem);
    const int tid = threadIdx.x;
    const int lane = tid & 31;
    const int warp = tid >> 5;
    const int t0 = blockIdx.x * 128;
    const int h = blockIdx.y;
    const int b = blockIdx.z;

    const size_t hoff = (size_t)(b * H_ + h);
    const __nv_bfloat16* qh = qh_g + (hoff * T_ + t0) * D_;
    const __nv_bfloat16* ql = ql_g + (hoff * T_ + t0) * D_;
    const __nv_bfloat16* kh = kh_g + hoff * S_ * D_;
    const __nv_bfloat16* kl = kl_g + hoff * S_ * D_;
    const __nv_bfloat16* vh = vh_g + hoff * S_ * D_;
    const __nv_bfloat16* vl = vl_g + hoff * S_ * D_;
    const float* kpf = kpf_g + b * S_;

    // Q tile load (128x64 hi/lo)
    #pragma unroll
    for (int i = 0; i < 8; i++) {
        const int id = tid + i * 256;
        const int sub = id >> 10;
        const int lin = id & 1023;
        const int row = lin >> 3;
        const int c   = lin & 7;
        cp16(sbase + sub * FA_OFF_QL + fa_off(row, c),
             (sub ? ql : qh) + (size_t)row * D_ + c * 8);
    }
    fa_load_stage(sbase, 0, kh, kl, vh, vl, kpf, 0, tid);
    cp_commit();

    const int wm = warp * 16;
    const int lrow = lane & 15;
    const int lseg = lane >> 4;
    const int qr = lane >> 2;         // frag row within 8
    const int qc = (lane & 3) * 2;    // frag col pair base
    const uint32_t ones = ((lane >> 2) == 0) ? 0x3F803F80u : 0u;

    float acc[8][4] = {};
    float lf[4] = {};
    float m0 = -1e30f, m1 = -1e30f;

    for (int tile = 0; tile < S_ / 64; tile++) {
        const int stg = tile & 1;
        if (tile < S_ / 64 - 1) {
            fa_load_stage(sbase, stg ^ 1, kh, kl, vh, vl, kpf, (tile + 1) * 64, tid);
            cp_commit();
            cp_wait<1>();
        } else {
            cp_wait<0>();
        }
        __syncthreads();

        const uint32_t stk = sbase + FA_OFF_ST + stg * FA_ST_B;

        // ---- scores: S = Qh Kh + Qh Kl + Ql Kh ----
        float sc[8][4];
        #pragma unroll
        for (int j = 0; j < 8; j++) {
            sc[j][0] = 0.f; sc[j][1] = 0.f; sc[j][2] = 0.f; sc[j][3] = 0.f;
        }
        #pragma unroll
        for (int kk = 0; kk < 4; kk++) {
            uint32_t ah[4], al[4];
            ldsm4(ah[0], ah[1], ah[2], ah[3],
                  sbase + fa_off(wm + lrow, kk * 2 + lseg));
            ldsm4(al[0], al[1], al[2], al[3],
                  sbase + FA_OFF_QL + fa_off(wm + lrow, kk * 2 + lseg));
            #pragma unroll
            for (int nb = 0; nb < 4; nb++) {
                uint32_t bh[4], bl[4];
                ldsm4(bh[0], bh[1], bh[2], bh[3],
                      stk + fa_off(nb * 16 + lrow, kk * 2 + lseg));
                ldsm4(bl[0], bl[1], bl[2], bl[3],
                      stk + 8192 + fa_off(nb * 16 + lrow, kk * 2 + lseg));
                #pragma unroll
                for (int hp = 0; hp < 2; hp++) {
                    float* sf = sc[nb * 2 + hp];
                    mma_bf16(sf, ah, bh[hp], bh[hp + 2]);
                    mma_bf16(sf, ah, bl[hp], bl[hp + 2]);
                    mma_bf16(sf, al, bh[hp], bh[hp + 2]);
                }
            }
        }

        // ---- masks ----
        const float* kpfs = (const float*)(smem + FA_OFF_KPF + stg * 256);
        const float* mrow0 = maskg + (size_t)(t0 + wm + qr) * S_ + tile * 64 + qc;
        const float* mrow1 = mrow0 + 8 * S_;
        #pragma unroll
        for (int j = 0; j < 8; j++) {
            float2 k2 = *(const float2*)&kpfs[j * 8 + qc];
            float2 a0 = *(const float2*)&mrow0[j * 8];
            float2 a1 = *(const float2*)&mrow1[j * 8];
            sc[j][0] += a0.x + k2.x; sc[j][1] += a0.y + k2.y;
            sc[j][2] += a1.x + k2.x; sc[j][3] += a1.y + k2.y;
        }

        // ---- online softmax ----
        float tm0 = -1e30f, tm1 = -1e30f;
        #pragma unroll
        for (int j = 0; j < 8; j++) {
            tm0 = fmaxf(tm0, fmaxf(sc[j][0], sc[j][1]));
            tm1 = fmaxf(tm1, fmaxf(sc[j][2], sc[j][3]));
        }
        tm0 = fmaxf(tm0, __shfl_xor_sync(0xffffffffu, tm0, 1, 4));
        tm0 = fmaxf(tm0, __shfl_xor_sync(0xffffffffu, tm0, 2, 4));
        tm1 = fmaxf(tm1, __shfl_xor_sync(0xffffffffu, tm1, 1, 4));
        tm1 = fmaxf(tm1, __shfl_xor_sync(0xffffffffu, tm1, 2, 4));
        const float mn0 = fmaxf(m0, tm0), mn1 = fmaxf(m1, tm1);
        const float cr0 = __expf(m0 - mn0), cr1 = __expf(m1 - mn1);
        m0 = mn0; m1 = mn1;
        #pragma unroll
        for (int j = 0; j < 8; j++) {
            sc[j][0] = __expf(sc[j][0] - mn0);
            sc[j][1] = __expf(sc[j][1] - mn0);
            sc[j][2] = __expf(sc[j][2] - mn1);
            sc[j][3] = __expf(sc[j][3] - mn1);
        }
        #pragma unroll
        for (int j = 0; j < 8; j++) {
            acc[j][0] *= cr0; acc[j][1] *= cr0;
            acc[j][2] *= cr1; acc[j][3] *= cr1;
        }
        lf[0] *= cr0; lf[1] *= cr0; lf[2] *= cr1; lf[3] *= cr1;

        // ---- PV: O += Ph Vh + Ph Vl + Pl Vh ; l += (Ph+Pl) @ ones ----
        #pragma unroll
        for (int kk = 0; kk < 4; kk++) {
            const int j0 = 2 * kk, j1 = j0 + 1;
            uint32_t ph[4], pl[4];
            {
                float px[8] = {sc[j0][0], sc[j0][1], sc[j0][2], sc[j0][3],
                               sc[j1][0], sc[j1][1], sc[j1][2], sc[j1][3]};
                #pragma unroll
                for (int q = 0; q < 4; q++) {
                    uint32_t hp_ = packbf(px[2 * q], px[2 * q + 1]);
                    float2 hf = unpackbf(hp_);
                    ph[q] = hp_;
                    pl[q] = packbf(px[2 * q] - hf.x, px[2 * q + 1] - hf.y);
                }
            }
            #pragma unroll
            for (int ng = 0; ng < 4; ng++) {
                uint32_t v4[4], w4[4];
                ldsm4t(v4, stk + 16384 + fa_off(kk * 16 + lrow, ng * 2 + lseg));
                ldsm4t(w4, stk + 24576 + fa_off(kk * 16 + lrow, ng * 2 + lseg));
                mma_bf16(acc[ng * 2 + 0], ph, v4[0], v4[1]);
                mma_bf16(acc[ng * 2 + 0], ph, w4[0], w4[1]);
                mma_bf16(acc[ng * 2 + 0], pl, v4[0], v4[1]);
                mma_bf16(acc[ng * 2 + 1], ph, v4[2], v4[3]);
                mma_bf16(acc[ng * 2 + 1], ph, w4[2], w4[3]);
                mma_bf16(acc[ng * 2 + 1], pl, v4[2], v4[3]);
            }
            mma_bf16(lf, ph, ones, ones);
            mma_bf16(lf, pl, ones, ones);
        }
        __syncthreads();
    }

    // ---- epilogue: normalize, write ctx bf16 hi/lo [t*B+b][E] ----
    const float l0 = __shfl_sync(0xffffffffu, lf[0], 0, 4);
    const float l1 = __shfl_sync(0xffffffffu, lf[2], 0, 4);
    const float inv0 = 1.f / l0, inv1 = 1.f / l1;
    const int r0 = t0 + wm + qr, r1 = r0 + 8;
    #pragma unroll
    for (int j = 0; j < 8; j++) {
        const int col = h * D_ + j * 8 + qc;
        {
            float x = acc[j][0] * inv0, y = acc[j][1] * inv0;
            uint32_t hp_ = packbf(x, y);
            float2 hf = unpackbf(hp_);
            uint32_t lp_ = packbf(x - hf.x, y - hf.y);
            const size_t idx = ((size_t)r0 * B_ + b) * E_ + col;
            *(uint32_t*)&ch[idx] = hp_;
            *(uint32_t*)&cl[idx] = lp_;
        }
        {
            float x = acc[j][2] * inv1, y = acc[j][3] * inv1;
            uint32_t hp_ = packbf(x, y);
            float2 hf = unpackbf(hp_);
            uint32_t lp_ = packbf(x - hf.x, y - hf.y);
            const size_t idx = ((size_t)r1 * B_ + b) * E_ + col;
            *(uint32_t*)&ch[idx] = hp_;
            *(uint32_t*)&cl[idx] = lp_;
        }
    }
}

// ---------------------------------------------------------------------------
// Launch
// ---------------------------------------------------------------------------
extern "C" void kernel_launch(void* const* d_in, const int* in_sizes, int n_in,
                              void* d_out, int out_size)
{
    const float* query = (const float*)d_in[0];
    const float* key   = (const float*)d_in[1];
    const float* value = (const float*)d_in[2];
    const float* amask = (const float*)d_in[3];
    const unsigned char* kpad = (const unsigned char*)d_in[4];
    const float* Wq = (const float*)d_in[5];
    const float* bq = (const float*)d_in[6];
    const float* Wk = (const float*)d_in[7];
    const float* bk = (const float*)d_in[8];
    const float* Wv = (const float*)d_in[9];
    const float* bv = (const float*)d_in[10];
    const float* Wo = (const float*)d_in[11];
    const float* bo = (const float*)d_in[12];
    float* out = (float*)d_out;

    __nv_bfloat16 *iqh, *iql, *ikh, *ikl, *ivh, *ivl, *wh, *wl;
    __nv_bfloat16 *pqh, *pql, *pkh, *pkl, *pvh, *pvl, *ch, *cl;
    float* kpf;
    cudaGetSymbolAddress((void**)&iqh, g_iqh); cudaGetSymbolAddress((void**)&iql, g_iql);
    cudaGetSymbolAddress((void**)&ikh, g_ikh); cudaGetSymbolAddress((void**)&ikl, g_ikl);
    cudaGetSymbolAddress((void**)&ivh, g_ivh); cudaGetSymbolAddress((void**)&ivl, g_ivl);
    cudaGetSymbolAddress((void**)&wh, g_wh);   cudaGetSymbolAddress((void**)&wl, g_wl);
    cudaGetSymbolAddress((void**)&pqh, g_pqh); cudaGetSymbolAddress((void**)&pql, g_pql);
    cudaGetSymbolAddress((void**)&pkh, g_pkh); cudaGetSymbolAddress((void**)&pkl, g_pkl);
    cudaGetSymbolAddress((void**)&pvh, g_pvh); cudaGetSymbolAddress((void**)&pvl, g_pvl);
    cudaGetSymbolAddress((void**)&ch, g_ch);   cudaGetSymbolAddress((void**)&cl, g_cl);
    cudaGetSymbolAddress((void**)&kpf, g_kpf);

    cudaFuncSetAttribute(gemm_tc<0>, cudaFuncAttributeMaxDynamicSharedMemorySize, GEMM_SMEM);
    cudaFuncSetAttribute(gemm_tc<1>, cudaFuncAttributeMaxDynamicSharedMemorySize, GEMM_SMEM);
    cudaFuncSetAttribute(flash_mma, cudaFuncAttributeMaxDynamicSharedMemorySize, FA_SMEM);

    const int nIn4 = M_ * E_ / 4;
    const int nW4  = E_ * E_ / 4;

    convert_hilo<<<(nIn4 + 255) / 256, 256>>>((const float4*)query, (uint2*)iqh, (uint2*)iql, nIn4);
    convert_hilo<<<(nIn4 + 255) / 256, 256>>>((const float4*)key,   (uint2*)ikh, (uint2*)ikl, nIn4);
    convert_hilo<<<(nIn4 + 255) / 256, 256>>>((const float4*)value, (uint2*)ivh, (uint2*)ivl, nIn4);
    convert_hilo<<<(nW4 + 255) / 256, 256>>>((const float4*)Wq, (uint2*)(wh + 0 * E_ * E_), (uint2*)(wl + 0 * E_ * E_), nW4);
    convert_hilo<<<(nW4 + 255) / 256, 256>>>((const float4*)Wk, (uint2*)(wh + 1 * E_ * E_), (uint2*)(wl + 1 * E_ * E_), nW4);
    convert_hilo<<<(nW4 + 255) / 256, 256>>>((const float4*)Wv, (uint2*)(wh + 2 * E_ * E_), (uint2*)(wl + 2 * E_ * E_), nW4);
    convert_hilo<<<(nW4 + 255) / 256, 256>>>((const float4*)Wo, (uint2*)(wh + 3 * E_ * E_), (uint2*)(wl + 3 * E_ * E_), nW4);
    kpad_to_float<<<(B_ * S_ + 255) / 256, 256>>>(kpad, kpf, B_ * S_);

    dim3 ggrid(M_ / 128, E_ / 128);
    gemm_tc<0><<<ggrid, 256, GEMM_SMEM>>>(iqh, iql, wh + 0 * E_ * E_, wl + 0 * E_ * E_, bq, nullptr, pqh, pql, 0.125f);
    gemm_tc<0><<<ggrid, 256, GEMM_SMEM>>>(ikh, ikl, wh + 1 * E_ * E_, wl + 1 * E_ * E_, bk, nullptr, pkh, pkl, 1.0f);
    gemm_tc<0><<<ggrid, 256, GEMM_SMEM>>>(ivh, ivl, wh + 2 * E_ * E_, wl + 2 * E_ * E_, bv, nullptr, pvh, pvl, 1.0f);

    dim3 fgrid(T_ / 128, H_, B_);
    flash_mma<<<fgrid, 256, FA_SMEM>>>(pqh, pql, pkh, pkl, pvh, pvl, amask, kpf, ch, cl);

    gemm_tc<1><<<ggrid, 256, GEMM_SMEM>>>(ch, cl, wh + 3 * E_ * E_, wl + 3 * E_ * E_, bo, out, nullptr, nullptr, 1.0f);
}

// round 5
// speedup vs baseline: 2.9296x; 1.0813x over previous
#include <cuda_runtime.h>
#include <cuda_bf16.h>
#include <cstdint>

// Problem constants (fixed shapes)
constexpr int T_ = 2048;
constexpr int S_ = 2048;
constexpr int B_ = 2;
constexpr int E_ = 1024;
constexpr int H_ = 16;
constexpr int D_ = 64;
constexpr int M_ = T_ * B_;   // 4096

// ---------------------------------------------------------------------------
// Scratch (__device__ globals; allocations forbidden)
// ---------------------------------------------------------------------------
__device__ __nv_bfloat16 g_iqh[M_ * E_], g_iql[M_ * E_];
__device__ __nv_bfloat16 g_ikh[M_ * E_], g_ikl[M_ * E_];
__device__ __nv_bfloat16 g_ivh[M_ * E_], g_ivl[M_ * E_];
__device__ __nv_bfloat16 g_wh[4][E_ * E_], g_wl[4][E_ * E_];
__device__ __nv_bfloat16 g_pqh[B_ * H_ * T_ * D_], g_pql[B_ * H_ * T_ * D_];
__device__ __nv_bfloat16 g_pkh[B_ * H_ * S_ * D_], g_pkl[B_ * H_ * S_ * D_];
__device__ __nv_bfloat16 g_pvh[B_ * H_ * S_ * D_], g_pvl[B_ * H_ * S_ * D_];
__device__ __nv_bfloat16 g_ch[M_ * E_], g_cl[M_ * E_];
__device__ float g_kpf[B_ * S_];

// ---------------------------------------------------------------------------
// PTX helpers (generic PTX only)
// ---------------------------------------------------------------------------
__device__ __forceinline__ uint32_t smem_u32(const void* p) {
    uint32_t a;
    asm("{ .reg .u64 t; cvta.to.shared.u64 t, %1; cvt.u32.u64 %0, t; }"
        : "=r"(a) : "l"(p));
    return a;
}
__device__ __forceinline__ void cp16(uint32_t dst, const void* src) {
    asm volatile("cp.async.cg.shared.global [%0], [%1], 16;" :: "r"(dst), "l"(src));
}
__device__ __forceinline__ void cp_commit() {
    asm volatile("cp.async.commit_group;" ::: "memory");
}
template <int N>
__device__ __forceinline__ void cp_wait() {
    asm volatile("cp.async.wait_group %0;" :: "n"(N) : "memory");
}
__device__ __forceinline__ void ldsm4(uint32_t& r0, uint32_t& r1, uint32_t& r2,
                                      uint32_t& r3, uint32_t addr) {
    asm volatile("ldmatrix.sync.aligned.m8n8.x4.shared.b16 {%0,%1,%2,%3}, [%4];"
                 : "=r"(r0), "=r"(r1), "=r"(r2), "=r"(r3) : "r"(addr));
}
__device__ __forceinline__ void ldsm4t(uint32_t* r, uint32_t addr) {
    asm volatile("ldmatrix.sync.aligned.m8n8.x4.trans.shared.b16 {%0,%1,%2,%3}, [%4];"
                 : "=r"(r[0]), "=r"(r[1]), "=r"(r[2]), "=r"(r[3]) : "r"(addr));
}
__device__ __forceinline__ void mma_bf16(float* c, const uint32_t* a,
                                         uint32_t b0, uint32_t b1) {
    asm volatile(
        "mma.sync.aligned.m16n8k16.row.col.f32.bf16.bf16.f32 "
        "{%0,%1,%2,%3}, {%4,%5,%6,%7}, {%8,%9}, {%0,%1,%2,%3};"
        : "+f"(c[0]), "+f"(c[1]), "+f"(c[2]), "+f"(c[3])
        : "r"(a[0]), "r"(a[1]), "r"(a[2]), "r"(a[3]), "r"(b0), "r"(b1));
}
__device__ __forceinline__ uint32_t packbf(float x, float y) {
    __nv_bfloat162 t = __floats2bfloat162_rn(x, y);
    return *reinterpret_cast<uint32_t*>(&t);
}
__device__ __forceinline__ float2 unpackbf(uint32_t u) {
    __nv_bfloat162 t = *reinterpret_cast<__nv_bfloat162*>(&u);
    return make_float2(__bfloat162float(t.x), __bfloat162float(t.y));
}

// ---------------------------------------------------------------------------
// Batched convert fp32 -> (bf16 hi, bf16 lo): 7 jobs in one launch
// ---------------------------------------------------------------------------
struct CvtJob { const float4* src; uint2* hi; uint2* lo; int n4; };
struct CvtJobs { CvtJob j[7]; };

__global__ void __launch_bounds__(256)
convert_all(CvtJobs jobs)
{
    const CvtJob jb = jobs.j[blockIdx.y];
    const int i = blockIdx.x * 256 + threadIdx.x;
    if (i >= jb.n4) return;
    float4 v = jb.src[i];
    __nv_bfloat16 h[4], l[4];
    float f[4] = {v.x, v.y, v.z, v.w};
    #pragma unroll
    for (int j = 0; j < 4; j++) {
        h[j] = __float2bfloat16(f[j]);
        l[j] = __float2bfloat16(f[j] - __bfloat162float(h[j]));
    }
    jb.hi[i] = *reinterpret_cast<uint2*>(h);
    jb.lo[i] = *reinterpret_cast<uint2*>(l);
}

__global__ void kpad_to_float(const unsigned char* __restrict__ kp,
                              float* __restrict__ out, int n)
{
    int i = blockIdx.x * 256 + threadIdx.x;
    if (i < n) out[i] = kp[i] ? -1e9f : 0.f;
}

// ---------------------------------------------------------------------------
// HMMA GEMM, tile 128(M) x 256(N), BK=32, 8 warps (warp tile 64x64).
// 3-term bf16 split: Ah*Wh + Ah*Wl + Al*Wh. One __syncthreads per chunk.
// OUT_MODE 0: bf16 hi/lo head-major [B,H,T,D]. OUT_MODE 1: fp32 [M,E].
// smem/stage: A hi/lo 16KB + W hi/lo 32KB = 48KB; 2 stages = 96KB.
// ---------------------------------------------------------------------------
struct GemmJob {
    const __nv_bfloat16 *Ah, *Al, *Wh, *Wl;
    const float* bias;
    __nv_bfloat16 *Chi, *Clo;
    float* Cf;
    float scale;
};
struct GemmJobs3 { GemmJob j[3]; };

constexpr int G_STAGE = 49152;
constexpr int G_SMEM  = 2 * G_STAGE;

__device__ __forceinline__ uint32_t sw_addr(int row, int byte_in_row) {
    uint32_t b = (uint32_t)(row * 64 + byte_in_row);
    return b ^ (((uint32_t)row & 3u) << 4);
}

__device__ __forceinline__ void g_load(
    uint32_t sdst, const GemmJob& jb, int bm, int bn, int k0, int tid)
{
    #pragma unroll
    for (int i = 0; i < 12; i++) {
        const int id = tid + i * 256;
        if (id < 1024) {
            const __nv_bfloat16* P = (id < 512) ? jb.Ah : jb.Al;
            const int lin = id & 511;
            const int row = lin >> 2, c = lin & 3;
            cp16(sdst + ((id < 512) ? 0u : 8192u) + sw_addr(row, c * 16),
                 P + (size_t)(bm + row) * E_ + k0 + c * 8);
        } else {
            const int idw = id - 1024;
            const __nv_bfloat16* P = (idw < 1024) ? jb.Wh : jb.Wl;
            const int lin = idw & 1023;
            const int row = lin >> 2, c = lin & 3;
            cp16(sdst + 16384u + ((idw < 1024) ? 0u : 16384u) + sw_addr(row, c * 16),
                 P + (size_t)(bn + row) * E_ + k0 + c * 8);
        }
    }
}

template <int OUT_MODE>
__global__ void __launch_bounds__(256, 1)
gemm_big(GemmJobs3 jobs)
{
    extern __shared__ char smem[];
    const uint32_t sbase = smem_u32(smem);
    const GemmJob jb = jobs.j[blockIdx.z];
    const int tid = threadIdx.x;
    const int warp = tid >> 5;
    const int lane = tid & 31;
    const int bm = blockIdx.x * 128;
    const int bn = blockIdx.y * 256;

    const int wm = (warp >> 2) * 64;
    const int wn = (warp & 3) * 64;

    float acc[4][8][4] = {};
    const int lrow = lane & 15;
    const int lseg = lane >> 4;

    g_load(sbase, jb, bm, bn, 0, tid);
    cp_commit();

    for (int chunk = 0; chunk < 32; chunk++) {
        const int s = chunk & 1;
        cp_wait<0>();
        __syncthreads();
        if (chunk < 31) {
            g_load(sbase + (s ^ 1) * G_STAGE, jb, bm, bn, (chunk + 1) * 32, tid);
            cp_commit();
        }
        const uint32_t st = sbase + s * G_STAGE;
        #pragma unroll
        for (int kk = 0; kk < 2; kk++) {
            const int c16 = (kk * 2 + lseg) * 16;
            uint32_t ah[4][4], al[4][4], bh[4][4], bl[4][4];
            #pragma unroll
            for (int mi = 0; mi < 4; mi++) {
                const uint32_t a = sw_addr(wm + mi * 16 + lrow, c16);
                ldsm4(ah[mi][0], ah[mi][1], ah[mi][2], ah[mi][3], st + a);
                ldsm4(al[mi][0], al[mi][1], al[mi][2], al[mi][3], st + 8192 + a);
            }
            #pragma unroll
            for (int nb = 0; nb < 4; nb++) {
                const uint32_t a = sw_addr(wn + nb * 16 + lrow, c16);
                ldsm4(bh[nb][0], bh[nb][1], bh[nb][2], bh[nb][3], st + 16384 + a);
                ldsm4(bl[nb][0], bl[nb][1], bl[nb][2], bl[nb][3], st + 32768 + a);
            }
            #pragma unroll
            for (int mi = 0; mi < 4; mi++) {
                #pragma unroll
                for (int ni = 0; ni < 8; ni++) {
                    const int nb = ni >> 1, hp = ni & 1;
                    mma_bf16(acc[mi][ni], ah[mi], bh[nb][hp], bh[nb][hp + 2]);
                    mma_bf16(acc[mi][ni], ah[mi], bl[nb][hp], bl[nb][hp + 2]);
                    mma_bf16(acc[mi][ni], al[mi], bh[nb][hp], bh[nb][hp + 2]);
                }
            }
        }
    }

    #pragma unroll
    for (int mi = 0; mi < 4; mi++) {
        #pragma unroll
        for (int ni = 0; ni < 8; ni++) {
            const int col = bn + wn + ni * 8 + (lane & 3) * 2;
            const float b0 = jb.bias[col], b1 = jb.bias[col + 1];
            #pragma unroll
            for (int half = 0; half < 2; half++) {
                const int m = bm + wm + mi * 16 + (lane >> 2) + half * 8;
                float ox = (acc[mi][ni][half * 2 + 0] + b0) * jb.scale;
                float oy = (acc[mi][ni][half * 2 + 1] + b1) * jb.scale;
                if (OUT_MODE == 0) {
                    const int t = m >> 1, b = m & 1;   // m = t*B + b, B=2
                    const int h = col >> 6, dd = col & 63;
                    const size_t idx = ((size_t)(b * H_ + h) * T_ + t) * D_ + dd;
                    uint32_t hp_ = packbf(ox, oy);
                    float2 hf = unpackbf(hp_);
                    uint32_t lp_ = packbf(ox - hf.x, oy - hf.y);
                    *(uint32_t*)&jb.Chi[idx] = hp_;
                    *(uint32_t*)&jb.Clo[idx] = lp_;
                } else {
                    *(float2*)&jb.Cf[(size_t)m * E_ + col] = make_float2(ox, oy);
                }
            }
        }
    }
}

// ---------------------------------------------------------------------------
// Flash attention via HMMA, 3-term hi/lo split for QK^T and PV.
// CTA: 128 q-rows of one (b,h); 8 warps x 16 rows; 64-key tiles, double buffer.
// smem: Q hi/lo 32KB | 2 x (K/V 32KB) | 2 x (mask 36KB, 288B rows) | 2 x kpf.
// One __syncthreads per tile; mask staged via cp.async.
// ---------------------------------------------------------------------------
constexpr uint32_t FA_OFF_QL  = 16384;
constexpr uint32_t FA_OFF_ST  = 32768;
constexpr uint32_t FA_ST_B    = 32768;
constexpr uint32_t FA_OFF_M   = 98304;
constexpr uint32_t FA_M_B     = 36864;   // 128 rows x 288 bytes
constexpr uint32_t FA_OFF_KPF = FA_OFF_M + 2 * FA_M_B;    // 172032
constexpr int FA_SMEM = (int)FA_OFF_KPF + 512;

__device__ __forceinline__ uint32_t fa_off(int row, int chunk) {
    return (uint32_t)(row * 128 + ((chunk ^ (row & 7)) << 4));
}

__device__ __forceinline__ void fa_load_stage(
    uint32_t sbase, int stage,
    const __nv_bfloat16* __restrict__ kh, const __nv_bfloat16* __restrict__ kl,
    const __nv_bfloat16* __restrict__ vh, const __nv_bfloat16* __restrict__ vl,
    const float* __restrict__ maskg, const float* __restrict__ kpf,
    int t0, int s0, int tid)
{
    const __nv_bfloat16* srcs[4] = {kh, kl, vh, vl};
    #pragma unroll
    for (int i = 0; i < 8; i++) {
        const int id = tid + i * 256;
        const int sub = id >> 9;
        const int lin = id & 511;
        const int row = lin >> 3;
        const int c   = lin & 7;
        cp16(sbase + FA_OFF_ST + stage * FA_ST_B + sub * 8192 + fa_off(row, c),
             srcs[sub] + (size_t)(s0 + row) * D_ + c * 8);
    }
    // mask tile: 128 rows x 64 fp32, row stride 288B in smem
    #pragma unroll
    for (int i = 0; i < 8; i++) {
        const int id = tid + i * 256;
        const int row = id >> 4;
        const int c16 = id & 15;
        cp16(sbase + FA_OFF_M + stage * FA_M_B + row * 288 + c16 * 16,
             maskg + (size_t)(t0 + row) * S_ + s0 + c16 * 4);
    }
    if (tid < 16)
        cp16(sbase + FA_OFF_KPF + stage * 256 + tid * 16, kpf + s0 + tid * 4);
}

__global__ void __launch_bounds__(256)
flash_mma(const __nv_bfloat16* __restrict__ qh_g, const __nv_bfloat16* __restrict__ ql_g,
          const __nv_bfloat16* __restrict__ kh_g, const __nv_bfloat16* __restrict__ kl_g,
          const __nv_bfloat16* __restrict__ vh_g, const __nv_bfloat16* __restrict__ vl_g,
          const float* __restrict__ maskg, const float* __restrict__ kpf_g,
          __nv_bfloat16* __restrict__ ch, __nv_bfloat16* __restrict__ cl)
{
    extern __shared__ char smem[];
    const uint32_t sbase = smem_u32(smem);
    const int tid = threadIdx.x;
    const int lane = tid & 31;
    const int warp = tid >> 5;
    const int t0 = blockIdx.x * 128;
    const int h = blockIdx.y;
    const int b = blockIdx.z;

    const size_t hoff = (size_t)(b * H_ + h);
    const __nv_bfloat16* qh = qh_g + (hoff * T_ + t0) * D_;
    const __nv_bfloat16* ql = ql_g + (hoff * T_ + t0) * D_;
    const __nv_bfloat16* kh = kh_g + hoff * S_ * D_;
    const __nv_bfloat16* kl = kl_g + hoff * S_ * D_;
    const __nv_bfloat16* vh = vh_g + hoff * S_ * D_;
    const __nv_bfloat16* vl = vl_g + hoff * S_ * D_;
    const float* kpf = kpf_g + b * S_;

    // Q tile load (128x64 hi/lo)
    #pragma unroll
    for (int i = 0; i < 8; i++) {
        const int id = tid + i * 256;
        const int sub = id >> 10;
        const int lin = id & 1023;
        const int row = lin >> 3;
        const int c   = lin & 7;
        cp16(sbase + sub * FA_OFF_QL + fa_off(row, c),
             (sub ? ql : qh) + (size_t)row * D_ + c * 8);
    }
    fa_load_stage(sbase, 0, kh, kl, vh, vl, maskg, kpf, t0, 0, tid);
    cp_commit();

    const int wm = warp * 16;
    const int lrow = lane & 15;
    const int lseg = lane >> 4;
    const int qr = lane >> 2;
    const int qc = (lane & 3) * 2;
    const uint32_t ones = ((lane >> 2) == 0) ? 0x3F803F80u : 0u;

    float acc[8][4] = {};
    float lf[4] = {};
    float m0 = -1e30f, m1 = -1e30f;

    for (int tile = 0; tile < S_ / 64; tile++) {
        const int stg = tile & 1;
        cp_wait<0>();
        __syncthreads();
        if (tile < S_ / 64 - 1) {
            fa_load_stage(sbase, stg ^ 1, kh, kl, vh, vl, maskg, kpf,
                          t0, (tile + 1) * 64, tid);
            cp_commit();
        }

        const uint32_t stk = sbase + FA_OFF_ST + stg * FA_ST_B;

        // ---- scores: S = Qh Kh + Qh Kl + Ql Kh ----
        float sc[8][4];
        #pragma unroll
        for (int j = 0; j < 8; j++) {
            sc[j][0] = 0.f; sc[j][1] = 0.f; sc[j][2] = 0.f; sc[j][3] = 0.f;
        }
        #pragma unroll
        for (int kk = 0; kk < 4; kk++) {
            uint32_t ah[4], al[4];
            ldsm4(ah[0], ah[1], ah[2], ah[3],
                  sbase + fa_off(wm + lrow, kk * 2 + lseg));
            ldsm4(al[0], al[1], al[2], al[3],
                  sbase + FA_OFF_QL + fa_off(wm + lrow, kk * 2 + lseg));
            #pragma unroll
            for (int nb = 0; nb < 4; nb++) {
                uint32_t bh[4], bl[4];
                ldsm4(bh[0], bh[1], bh[2], bh[3],
                      stk + fa_off(nb * 16 + lrow, kk * 2 + lseg));
                ldsm4(bl[0], bl[1], bl[2], bl[3],
                      stk + 8192 + fa_off(nb * 16 + lrow, kk * 2 + lseg));
                #pragma unroll
                for (int hp = 0; hp < 2; hp++) {
                    float* sf = sc[nb * 2 + hp];
                    mma_bf16(sf, ah, bh[hp], bh[hp + 2]);
                    mma_bf16(sf, ah, bl[hp], bl[hp + 2]);
                    mma_bf16(sf, al, bh[hp], bh[hp + 2]);
                }
            }
        }

        // ---- masks (from smem) ----
        const float* kpfs = (const float*)(smem + FA_OFF_KPF + stg * 256);
        const float* ms   = (const float*)(smem + FA_OFF_M + stg * FA_M_B);
        const int r0s = (wm + qr) * 72, r1s = r0s + 8 * 72;
        #pragma unroll
        for (int j = 0; j < 8; j++) {
            float2 k2 = *(const float2*)&kpfs[j * 8 + qc];
            float2 a0 = *(const float2*)&ms[r0s + j * 8 + qc];
            float2 a1 = *(const float2*)&ms[r1s + j * 8 + qc];
            sc[j][0] += a0.x + k2.x; sc[j][1] += a0.y + k2.y;
            sc[j][2] += a1.x + k2.x; sc[j][3] += a1.y + k2.y;
        }

        // ---- online softmax ----
        float tm0 = -1e30f, tm1 = -1e30f;
        #pragma unroll
        for (int j = 0; j < 8; j++) {
            tm0 = fmaxf(tm0, fmaxf(sc[j][0], sc[j][1]));
            tm1 = fmaxf(tm1, fmaxf(sc[j][2], sc[j][3]));
        }
        tm0 = fmaxf(tm0, __shfl_xor_sync(0xffffffffu, tm0, 1, 4));
        tm0 = fmaxf(tm0, __shfl_xor_sync(0xffffffffu, tm0, 2, 4));
        tm1 = fmaxf(tm1, __shfl_xor_sync(0xffffffffu, tm1, 1, 4));
        tm1 = fmaxf(tm1, __shfl_xor_sync(0xffffffffu, tm1, 2, 4));
        const float mn0 = fmaxf(m0, tm0), mn1 = fmaxf(m1, tm1);
        const float cr0 = __expf(m0 - mn0), cr1 = __expf(m1 - mn1);
        m0 = mn0; m1 = mn1;
        #pragma unroll
        for (int j = 0; j < 8; j++) {
            sc[j][0] = __expf(sc[j][0] - mn0);
            sc[j][1] = __expf(sc[j][1] - mn0);
            sc[j][2] = __expf(sc[j][2] - mn1);
            sc[j][3] = __expf(sc[j][3] - mn1);
        }
        #pragma unroll
        for (int j = 0; j < 8; j++) {
            acc[j][0] *= cr0; acc[j][1] *= cr0;
            acc[j][2] *= cr1; acc[j][3] *= cr1;
        }
        lf[0] *= cr0; lf[1] *= cr0; lf[2] *= cr1; lf[3] *= cr1;

        // ---- PV: O += Ph Vh + Ph Vl + Pl Vh ; l += (Ph+Pl) @ ones ----
        #pragma unroll
        for (int kk = 0; kk < 4; kk++) {
            const int j0 = 2 * kk, j1 = j0 + 1;
            uint32_t ph[4], pl[4];
            {
                float px[8] = {sc[j0][0], sc[j0][1], sc[j0][2], sc[j0][3],
                               sc[j1][0], sc[j1][1], sc[j1][2], sc[j1][3]};
                #pragma unroll
                for (int q = 0; q < 4; q++) {
                    uint32_t hp_ = packbf(px[2 * q], px[2 * q + 1]);
                    float2 hf = unpackbf(hp_);
                    ph[q] = hp_;
                    pl[q] = packbf(px[2 * q] - hf.x, px[2 * q + 1] - hf.y);
                }
            }
            #pragma unroll
            for (int ng = 0; ng < 4; ng++) {
                uint32_t v4[4], w4[4];
                ldsm4t(v4, stk + 16384 + fa_off(kk * 16 + lrow, ng * 2 + lseg));
                ldsm4t(w4, stk + 24576 + fa_off(kk * 16 + lrow, ng * 2 + lseg));
                mma_bf16(acc[ng * 2 + 0], ph, v4[0], v4[1]);
                mma_bf16(acc[ng * 2 + 0], ph, w4[0], w4[1]);
                mma_bf16(acc[ng * 2 + 0], pl, v4[0], v4[1]);
                mma_bf16(acc[ng * 2 + 1], ph, v4[2], v4[3]);
                mma_bf16(acc[ng * 2 + 1], ph, w4[2], w4[3]);
                mma_bf16(acc[ng * 2 + 1], pl, v4[2], v4[3]);
            }
            mma_bf16(lf, ph, ones, ones);
            mma_bf16(lf, pl, ones, ones);
        }
    }

    // ---- epilogue: normalize, write ctx bf16 hi/lo [t*B+b][E] ----
    const float l0 = __shfl_sync(0xffffffffu, lf[0], 0, 4);
    const float l1 = __shfl_sync(0xffffffffu, lf[2], 0, 4);
    const float inv0 = 1.f / l0, inv1 = 1.f / l1;
    const int r0 = t0 + wm + qr, r1 = r0 + 8;
    #pragma unroll
    for (int j = 0; j < 8; j++) {
        const int col = h * D_ + j * 8 + qc;
        {
            float x = acc[j][0] * inv0, y = acc[j][1] * inv0;
            uint32_t hp_ = packbf(x, y);
            float2 hf = unpackbf(hp_);
            uint32_t lp_ = packbf(x - hf.x, y - hf.y);
            const size_t idx = ((size_t)r0 * B_ + b) * E_ + col;
            *(uint32_t*)&ch[idx] = hp_;
            *(uint32_t*)&cl[idx] = lp_;
        }
        {
            float x = acc[j][2] * inv1, y = acc[j][3] * inv1;
            uint32_t hp_ = packbf(x, y);
            float2 hf = unpackbf(hp_);
            uint32_t lp_ = packbf(x - hf.x, y - hf.y);
            const size_t idx = ((size_t)r1 * B_ + b) * E_ + col;
            *(uint32_t*)&ch[idx] = hp_;
            *(uint32_t*)&cl[idx] = lp_;
        }
    }
}

// ---------------------------------------------------------------------------
// Launch
// ---------------------------------------------------------------------------
extern "C" void kernel_launch(void* const* d_in, const int* in_sizes, int n_in,
                              void* d_out, int out_size)
{
    const float* query = (const float*)d_in[0];
    const float* key   = (const float*)d_in[1];
    const float* value = (const float*)d_in[2];
    const float* amask = (const float*)d_in[3];
    const unsigned char* kpad = (const unsigned char*)d_in[4];
    const float* Wq = (const float*)d_in[5];
    const float* bq = (const float*)d_in[6];
    const float* Wk = (const float*)d_in[7];
    const float* bk = (const float*)d_in[8];
    const float* Wv = (const float*)d_in[9];
    const float* bv = (const float*)d_in[10];
    const float* Wo = (const float*)d_in[11];
    const float* bo = (const float*)d_in[12];
    float* out = (float*)d_out;

    __nv_bfloat16 *iqh, *iql, *ikh, *ikl, *ivh, *ivl, *wh, *wl;
    __nv_bfloat16 *pqh, *pql, *pkh, *pkl, *pvh, *pvl, *ch, *cl;
    float* kpf;
    cudaGetSymbolAddress((void**)&iqh, g_iqh); cudaGetSymbolAddress((void**)&iql, g_iql);
    cudaGetSymbolAddress((void**)&ikh, g_ikh); cudaGetSymbolAddress((void**)&ikl, g_ikl);
    cudaGetSymbolAddress((void**)&ivh, g_ivh); cudaGetSymbolAddress((void**)&ivl, g_ivl);
    cudaGetSymbolAddress((void**)&wh, g_wh);   cudaGetSymbolAddress((void**)&wl, g_wl);
    cudaGetSymbolAddress((void**)&pqh, g_pqh); cudaGetSymbolAddress((void**)&pql, g_pql);
    cudaGetSymbolAddress((void**)&pkh, g_pkh); cudaGetSymbolAddress((void**)&pkl, g_pkl);
    cudaGetSymbolAddress((void**)&pvh, g_pvh); cudaGetSymbolAddress((void**)&pvl, g_pvl);
    cudaGetSymbolAddress((void**)&ch, g_ch);   cudaGetSymbolAddress((void**)&cl, g_cl);
    cudaGetSymbolAddress((void**)&kpf, g_kpf);

    cudaFuncSetAttribute(gemm_big<0>, cudaFuncAttributeMaxDynamicSharedMemorySize, G_SMEM);
    cudaFuncSetAttribute(gemm_big<1>, cudaFuncAttributeMaxDynamicSharedMemorySize, G_SMEM);
    cudaFuncSetAttribute(flash_mma, cudaFuncAttributeMaxDynamicSharedMemorySize, FA_SMEM);

    const int nIn4 = M_ * E_ / 4;    // 1,048,576
    const int nW4  = E_ * E_ / 4;    // 262,144

    // batched converts (7 jobs, one launch)
    CvtJobs cj;
    cj.j[0] = {(const float4*)query, (uint2*)iqh, (uint2*)iql, nIn4};
    cj.j[1] = {(const float4*)key,   (uint2*)ikh, (uint2*)ikl, nIn4};
    cj.j[2] = {(const float4*)value, (uint2*)ivh, (uint2*)ivl, nIn4};
    cj.j[3] = {(const float4*)Wq, (uint2*)(wh + 0 * E_ * E_), (uint2*)(wl + 0 * E_ * E_), nW4};
    cj.j[4] = {(const float4*)Wk, (uint2*)(wh + 1 * E_ * E_), (uint2*)(wl + 1 * E_ * E_), nW4};
    cj.j[5] = {(const float4*)Wv, (uint2*)(wh + 2 * E_ * E_), (uint2*)(wl + 2 * E_ * E_), nW4};
    cj.j[6] = {(const float4*)Wo, (uint2*)(wh + 3 * E_ * E_), (uint2*)(wl + 3 * E_ * E_), nW4};
    convert_all<<<dim3(nIn4 / 256, 7), 256>>>(cj);
    kpad_to_float<<<(B_ * S_ + 255) / 256, 256>>>(kpad, kpf, B_ * S_);

    // fused QKV projections (grid.z = 3), head-major bf16 hi/lo outputs
    GemmJobs3 gq;
    gq.j[0] = {iqh, iql, wh + 0 * E_ * E_, wl + 0 * E_ * E_, bq, pqh, pql, nullptr, 0.125f};
    gq.j[1] = {ikh, ikl, wh + 1 * E_ * E_, wl + 1 * E_ * E_, bk, pkh, pkl, nullptr, 1.0f};
    gq.j[2] = {ivh, ivl, wh + 2 * E_ * E_, wl + 2 * E_ * E_, bv, pvh, pvl, nullptr, 1.0f};
    gemm_big<0><<<dim3(M_ / 128, E_ / 256, 3), 256, G_SMEM>>>(gq);

    // flash attention
    dim3 fgrid(T_ / 128, H_, B_);
    flash_mma<<<fgrid, 256, FA_SMEM>>>(pqh, pql, pkh, pkl, pvh, pvl, amask, kpf, ch, cl);

    // output projection (fp32 out)
    GemmJobs3 go;
    go.j[0] = {ch, cl, wh + 3 * E_ * E_, wl + 3 * E_ * E_, bo, nullptr, nullptr, out, 1.0f};
    go.j[1] = go.j[0];
    go.j[2] = go.j[0];
    gemm_big<1><<<dim3(M_ / 128, E_ / 256, 1), 256, G_SMEM>>>(go);
}